// round 10
// baseline (speedup 1.0000x reference)
#include <cuda_runtime.h>
#include <cuda_bf16.h>
#include <cstdint>

// Problem constants (B=4, S=2048, D=16, HEADS=16, HEAD_SIZE=1)
#define BB   4
#define SS   2048
#define DD   16
#define NPAIR (BB * DD)          // 64 (b,h) pairs
#define HALF (SS / 2)            // 1024 rows per sub-block
#define NC   23                  // polynomial coefficients (degree 22)

// ---------------------------------------------------------------------------
// Kernel 0: initialize out with the output bias (out is poisoned by harness).
// ---------------------------------------------------------------------------
__global__ void __launch_bounds__(512) init_out_kernel(
    const float* __restrict__ b_out, float* __restrict__ out)
{
    int g = blockIdx.x * 512 + threadIdx.x;      // 0 .. 131071
    out[g] = __ldg(b_out + (g & 15));
}

// ---------------------------------------------------------------------------
// Kernel 1: fused QKV + polynomial causal softmax-attention + out-projection.
// grid 128 = 64 pairs x 2 sub-blocks (one block per SM), 512 threads.
// Scalar-head trick: e^{q k} = sum_p q^p/p! k^p is separable; causal attention
// = prefix sums of moments M_p[i] = sum_{j<=i} k_j^p (v_j).
// sub=0 scans rows [0,1024); sub=1 redundantly REDUCES first-half totals from
// x, then scans rows [1024,2048). Everything register-resident; per-thread
// 2 rows; warp shfl-scan + warp-carry. Output: att * w_out[h][:] atomically
// accumulated into out (bias pre-initialized by kernel 0).
// ---------------------------------------------------------------------------
__global__ void __launch_bounds__(512) attn_poly_kernel(
    const float* __restrict__ x,      // [B, S, D]
    const float* __restrict__ w,      // [16, 48] row-major
    const float* __restrict__ bias,   // [48]
    const float* __restrict__ w_out,  // [16, 16] row-major
    float* __restrict__ out)          // [B*S, 16]
{
    __shared__ float swq[DD], swk[DD], swv[DD], swo[DD];
    __shared__ float sb3[3];
    __shared__ float sWT[16][NC + 1];     // warp totals / pre-reduce scratch
    __shared__ float sWC[16][NC + 1];     // warp exclusive carries
    __shared__ float sbase[NC + 1];       // first-half totals (sub=1)

    const float INVF[NC] = {
        1.0f, 1.0f, 0.5f, 1.6666667e-1f, 4.1666668e-2f, 8.3333338e-3f,
        1.3888889e-3f, 1.9841270e-4f, 2.4801588e-5f, 2.7557319e-6f,
        2.7557319e-7f, 2.5052108e-8f, 2.0876757e-9f, 1.6059044e-10f,
        1.1470746e-11f, 7.6471637e-13f, 4.7794773e-14f, 2.8114573e-15f,
        1.5619207e-16f, 8.2206352e-18f, 4.1103176e-19f, 1.9572941e-20f,
        8.8967914e-22f };

    int bid  = blockIdx.x;
    int pair = bid >> 1;
    int sub  = bid & 1;
    int b_idx = pair >> 4;
    int h_idx = pair & 15;
    int t = threadIdx.x, lane = t & 31, wrp = t >> 5;

    if (t < DD) {
        swq[t] = w[t * 48 + h_idx];
        swk[t] = w[t * 48 + 16 + h_idx];
        swv[t] = w[t * 48 + 32 + h_idx];
        swo[t] = w_out[h_idx * 16 + t];
    }
    if (t < 3) sb3[t] = bias[t * 16 + h_idx];
    __syncthreads();

    float bq = sb3[0], bk = sb3[1], bv = sb3[2];
    const float4* xb = reinterpret_cast<const float4*>(x + (size_t)b_idx * SS * DD);

    // --- own rows: r0 = base + 2t, r1 = r0 + 1 ---
    int base = sub * HALF;
    int r0 = base + 2 * t, r1 = r0 + 1;

    float q0, k0, v0, q1, k1, v1;
    {
        float xr[DD];
        #pragma unroll
        for (int q4 = 0; q4 < 4; q4++) {
            float4 t4 = xb[r0 * 4 + q4];
            xr[q4*4+0]=t4.x; xr[q4*4+1]=t4.y; xr[q4*4+2]=t4.z; xr[q4*4+3]=t4.w;
        }
        q0 = bq; k0 = bk; v0 = bv;
        #pragma unroll
        for (int d = 0; d < DD; d++) {
            q0 = fmaf(xr[d], swq[d], q0);
            k0 = fmaf(xr[d], swk[d], k0);
            v0 = fmaf(xr[d], swv[d], v0);
        }
        #pragma unroll
        for (int q4 = 0; q4 < 4; q4++) {
            float4 t4 = xb[r1 * 4 + q4];
            xr[q4*4+0]=t4.x; xr[q4*4+1]=t4.y; xr[q4*4+2]=t4.z; xr[q4*4+3]=t4.w;
        }
        q1 = bq; k1 = bk; v1 = bv;
        #pragma unroll
        for (int d = 0; d < DD; d++) {
            q1 = fmaf(xr[d], swq[d], q1);
            k1 = fmaf(xr[d], swk[d], k1);
            v1 = fmaf(xr[d], swv[d], v1);
        }
    }

    // --- pre rows (first half) for sub=1: k,v only ---
    float pk0 = 0.f, pv0 = 0.f, pk1 = 0.f, pv1 = 0.f;
    if (sub) {
        int p0 = 2 * t, p1 = p0 + 1;
        float xr[DD];
        #pragma unroll
        for (int q4 = 0; q4 < 4; q4++) {
            float4 t4 = xb[p0 * 4 + q4];
            xr[q4*4+0]=t4.x; xr[q4*4+1]=t4.y; xr[q4*4+2]=t4.z; xr[q4*4+3]=t4.w;
        }
        pk0 = bk; pv0 = bv;
        #pragma unroll
        for (int d = 0; d < DD; d++) {
            pk0 = fmaf(xr[d], swk[d], pk0);
            pv0 = fmaf(xr[d], swv[d], pv0);
        }
        #pragma unroll
        for (int q4 = 0; q4 < 4; q4++) {
            float4 t4 = xb[p1 * 4 + q4];
            xr[q4*4+0]=t4.x; xr[q4*4+1]=t4.y; xr[q4*4+2]=t4.z; xr[q4*4+3]=t4.w;
        }
        pk1 = bk; pv1 = bv;
        #pragma unroll
        for (int d = 0; d < DD; d++) {
            pk1 = fmaf(xr[d], swk[d], pk1);
            pv1 = fmaf(xr[d], swv[d], pv1);
        }
    }

    float den0, den1;            // this thread's two row denominators
    float* orow0 = out + (size_t)(b_idx * SS + r0) * DD;
    float* orow1 = out + (size_t)(b_idx * SS + r1) * DD;

    // ====================== two phases: 0 = den, 1 = num ======================
    #pragma unroll
    for (int phase = 0; phase < 2; phase++) {
        float m0 = phase ? v0 : 1.f;      // own-row moment weights
        float m1 = phase ? v1 : 1.f;
        float pm0 = phase ? pv0 : 1.f;    // pre-row moment weights
        float pm1 = phase ? pv1 : 1.f;

        // --- pre-half total reduction (sub=1 only; block-uniform branch) ---
        float pre[NC];
        if (sub) {
            float Tp[NC];
            {
                float kp = 1.f;
                #pragma unroll
                for (int p = 0; p < NC; p++) { Tp[p] = kp * pm0; kp *= pk0; }
                kp = 1.f;
                #pragma unroll
                for (int p = 0; p < NC; p++) { Tp[p] = fmaf(kp, pm1, Tp[p]); kp *= pk1; }
            }
            #pragma unroll
            for (int off = 16; off; off >>= 1)
                #pragma unroll
                for (int p = 0; p < NC; p++)
                    Tp[p] += __shfl_xor_sync(0xffffffffu, Tp[p], off);
            if (lane == 0)
                #pragma unroll
                for (int p = 0; p < NC; p++) sWT[wrp][p] = Tp[p];
            __syncthreads();
            if (wrp == 0 && lane < NC) {
                float s = 0.f;
                #pragma unroll
                for (int w16 = 0; w16 < 16; w16++) s += sWT[w16][lane];
                sbase[lane] = s;
            }
            __syncthreads();
            #pragma unroll
            for (int p = 0; p < NC; p++) pre[p] = sbase[p];
            __syncthreads();   // protect sbase/sWT before reuse next phase
        } else {
            #pragma unroll
            for (int p = 0; p < NC; p++) pre[p] = 0.f;
        }

        // --- serial moments of own 2 rows ---
        float T[NC];
        {
            float kp = 1.f;
            #pragma unroll
            for (int p = 0; p < NC; p++) { T[p] = kp * m0; kp *= k0; }
            kp = 1.f;
            #pragma unroll
            for (int p = 0; p < NC; p++) { T[p] = fmaf(kp, m1, T[p]); kp *= k1; }
        }

        // --- warp inclusive scan over lanes ---
        #pragma unroll
        for (int d = 1; d < 32; d <<= 1)
            #pragma unroll
            for (int p = 0; p < NC; p++) {
                float o = __shfl_up_sync(0xffffffffu, T[p], d);
                if (lane >= d) T[p] += o;
            }
        if (lane == 31)
            #pragma unroll
            for (int p = 0; p < NC; p++) sWT[wrp][p] = T[p];
        __syncthreads();
        if (wrp == 0 && lane < NC) {
            float c = 0.f;
            #pragma unroll
            for (int w16 = 0; w16 < 16; w16++) {
                float tot = sWT[w16][lane];
                sWC[w16][lane] = c;
                c += tot;
            }
        }
        __syncthreads();

        // --- exclusive prefix for this thread (before row r0) ---
        float A[NC];
        #pragma unroll
        for (int p = 0; p < NC; p++) {
            float o = __shfl_up_sync(0xffffffffu, T[p], 1);
            A[p] = pre[p] + sWC[wrp][p] + (lane ? o : 0.f);
        }
        __syncthreads();   // sWT/sWC reuse safety for next phase

        // --- passB: include own rows, evaluate polynomial ---
        {
            float kp = 1.f;
            #pragma unroll
            for (int p = 0; p < NC; p++) { A[p] = fmaf(kp, m0, A[p]); kp *= k0; }
            float qp = 1.f, acc = 0.f;
            #pragma unroll
            for (int p = 0; p < NC; p++) { acc = fmaf(A[p] * INVF[p], qp, acc); qp *= q0; }
            if (phase == 0) den0 = acc;
            else {
                float att = acc / den0;
                #pragma unroll
                for (int d = 0; d < DD; d++) atomicAdd(orow0 + d, att * swo[d]);
            }

            kp = 1.f;
            #pragma unroll
            for (int p = 0; p < NC; p++) { A[p] = fmaf(kp, m1, A[p]); kp *= k1; }
            qp = 1.f; acc = 0.f;
            #pragma unroll
            for (int p = 0; p < NC; p++) { acc = fmaf(A[p] * INVF[p], qp, acc); qp *= q1; }
            if (phase == 0) den1 = acc;
            else {
                float att = acc / den1;
                #pragma unroll
                for (int d = 0; d < DD; d++) atomicAdd(orow1 + d, att * swo[d]);
            }
        }
    }
}

// ---------------------------------------------------------------------------
extern "C" void kernel_launch(void* const* d_in, const int* in_sizes, int n_in,
                              void* d_out, int out_size)
{
    const float* x     = (const float*)d_in[0];
    const float* w_qkv = (const float*)d_in[1];
    const float* b_qkv = (const float*)d_in[2];
    const float* w_out = (const float*)d_in[3];
    const float* b_out = (const float*)d_in[4];
    float* out = (float*)d_out;

    init_out_kernel<<<(BB * SS * DD) / 512, 512>>>(b_out, out);
    attn_poly_kernel<<<2 * NPAIR, 512>>>(x, w_qkv, b_qkv, w_out, out);
}